// round 4
// baseline (speedup 1.0000x reference)
#include <cuda_runtime.h>
#include <cstdint>

typedef unsigned long long u64;

// ---- packed f32x2 helpers (sm_103a) ----
__device__ __forceinline__ u64 pack2(float lo, float hi) {
    u64 r;
    asm("mov.b64 %0, {%1, %2};" : "=l"(r) : "f"(lo), "f"(hi));
    return r;
}
__device__ __forceinline__ float2 unpack2(u64 v) {
    float2 f;
    asm("mov.b64 {%0, %1}, %2;" : "=f"(f.x), "=f"(f.y) : "l"(v));
    return f;
}
__device__ __forceinline__ void fma2(u64& d, u64 a, u64 b, u64 c) {
    asm("fma.rn.f32x2 %0, %1, %2, %3;" : "=l"(d) : "l"(a), "l"(b), "l"(c));
}

// ---- single-instruction tanh (MUFU.TANH) ----
__device__ __forceinline__ float tanha(float x) {
    float r;
    asm("tanh.approx.f32 %0, %1;" : "=f"(r) : "f"(x));
    return r;
}
// sigmoid(z) = 0.5*tanh(z/2) + 0.5 ; /2 pre-folded into weights.
__device__ __forceinline__ float sig_prescaled(float half_z) {
    return fmaf(tanha(half_z), 0.5f, 0.5f);
}

// 8 threads per sequence-PAIR (A,B). Thread hid owns hidden unit hid of both
// layers. Gates are per-gate k-vectorized f32x2 accumulators (4 independent
// chains per seq-layer). Hidden-state exchange goes through shared memory:
// STS.32 scalars, LDS.128 pre-paired operands (broadcast within 8-lane group,
// conflict-free across groups via 160B stride). No shuffles in the hot loop.
__global__ void __launch_bounds__(128) lstm_fused4(
    const float* __restrict__ input,
    const float* __restrict__ w_ih0, const float* __restrict__ w_hh0,
    const float* __restrict__ b_ih0, const float* __restrict__ b_hh0,
    const float* __restrict__ w_ih1, const float* __restrict__ w_hh1,
    const float* __restrict__ b_ih1, const float* __restrict__ b_hh1,
    const float* __restrict__ w_mlp, const float* __restrict__ b_mlp,
    float* __restrict__ out, int B)
{
    const int T = 256;
    // per-group 40 floats (160B stride: groups land on disjoint bank sets)
    // layout within group: h0A[8] @0, h0B[8] @8, h1A[8] @16, h1B[8] @24, pad.
    __shared__ float hx[16 * 40];

    int tid  = blockIdx.x * blockDim.x + threadIdx.x;
    int grp  = tid >> 3;
    int hid  = tid & 7;
    int half = B >> 1;
    if (grp >= half) return;

    float* gp = &hx[(threadIdx.x >> 3) * 40];

    int bA = grp;
    int bB = grp + half;

    // ---- weights in registers, per-gate k-pairs; i,f,o rows prescaled 0.5 ----
    // gate index g: 0=i,1=f,2=g,3=o ; row = g*8 + hid ; scale = (g==2)?1:0.5
    u64 wx0[4];          // layer0 x-pair per gate
    u64 wh0[4][4];       // layer0 h-pairs
    u64 wi1[4][4];       // layer1 h0-pairs
    u64 wh1[4][4];       // layer1 h1-pairs
    u64 bias0[4], bias1[4];
#pragma unroll
    for (int g = 0; g < 4; g++) {
        int row = g * 8 + hid;
        float s = (g == 2) ? 1.0f : 0.5f;
        wx0[g] = pack2(s * w_ih0[row*2+0], s * w_ih0[row*2+1]);
#pragma unroll
        for (int j = 0; j < 4; j++) {
            wh0[g][j] = pack2(s * w_hh0[row*8+2*j], s * w_hh0[row*8+2*j+1]);
            wi1[g][j] = pack2(s * w_ih1[row*8+2*j], s * w_ih1[row*8+2*j+1]);
            wh1[g][j] = pack2(s * w_hh1[row*8+2*j], s * w_hh1[row*8+2*j+1]);
        }
        bias0[g] = pack2(s * (b_ih0[row] + b_hh0[row]), 0.0f);
        bias1[g] = pack2(s * (b_ih1[row] + b_hh1[row]), 0.0f);
    }

    const float2* xbA = reinterpret_cast<const float2*>(input) + (size_t)bA * T;
    const float2* xbB = reinterpret_cast<const float2*>(input) + (size_t)bB * T;
    float2 xA = xbA[0];
    float2 xB = xbB[0];

    float c0A = 0.f, h0A = 0.f, c1A = 0.f, h1A = 0.f;
    float c0B = 0.f, h0B = 0.f, c1B = 0.f, h1B = 0.f;

    // zero the exchange slots (h0(-1), h1(-1) = 0)
    gp[0  + hid] = 0.f;
    gp[8  + hid] = 0.f;
    gp[16 + hid] = 0.f;
    gp[24 + hid] = 0.f;
    __syncwarp();

    for (int t = 0; t < T; t++) {
        // ---- load h0(t-1) pairs for layer 0 ----
        float4 pa0 = *reinterpret_cast<const float4*>(gp + 0);
        float4 pa1 = *reinterpret_cast<const float4*>(gp + 4);
        float4 pb0 = *reinterpret_cast<const float4*>(gp + 8);
        float4 pb1 = *reinterpret_cast<const float4*>(gp + 12);
        u64 hA[4] = { pack2(pa0.x,pa0.y), pack2(pa0.z,pa0.w),
                      pack2(pa1.x,pa1.y), pack2(pa1.z,pa1.w) };
        u64 hB[4] = { pack2(pb0.x,pb0.y), pack2(pb0.z,pb0.w),
                      pack2(pb1.x,pb1.y), pack2(pb1.z,pb1.w) };

        // ================= layer 0: 4 gate chains per seq =================
        u64 xpA = pack2(xA.x, xA.y);
        u64 xpB = pack2(xB.x, xB.y);
        u64 aA[4], aB[4];
#pragma unroll
        for (int g = 0; g < 4; g++) {
            fma2(aA[g], xpA, wx0[g], bias0[g]);
            fma2(aB[g], xpB, wx0[g], bias0[g]);
        }
#pragma unroll
        for (int j = 0; j < 4; j++) {
#pragma unroll
            for (int g = 0; g < 4; g++) {
                fma2(aA[g], hA[j], wh0[g][j], aA[g]);
                fma2(aB[g], hB[j], wh0[g][j], aB[g]);
            }
        }
        {
            float2 vi, vf, vg, vo;
            vi = unpack2(aA[0]); vf = unpack2(aA[1]);
            vg = unpack2(aA[2]); vo = unpack2(aA[3]);
            float iA = sig_prescaled(vi.x + vi.y);
            float fA = sig_prescaled(vf.x + vf.y);
            float gA = tanha(vg.x + vg.y);
            float oA = sig_prescaled(vo.x + vo.y);
            c0A = fmaf(fA, c0A, iA * gA);
            h0A = oA * tanha(c0A);

            vi = unpack2(aB[0]); vf = unpack2(aB[1]);
            vg = unpack2(aB[2]); vo = unpack2(aB[3]);
            float iB = sig_prescaled(vi.x + vi.y);
            float fB = sig_prescaled(vf.x + vf.y);
            float gB = tanha(vg.x + vg.y);
            float oB = sig_prescaled(vo.x + vo.y);
            c0B = fmaf(fB, c0B, iB * gB);
            h0B = oB * tanha(c0B);
        }

        // prefetch next x
        int tn = (t < T - 1) ? (t + 1) : t;
        xA = xbA[tn];
        xB = xbB[tn];

        __syncwarp();                 // all lanes done reading h0(t-1)
        gp[0 + hid] = h0A;
        gp[8 + hid] = h0B;
        __syncwarp();                 // h0(t) visible

        // ---- load h0(t) and h1(t-1) pairs for layer 1 ----
        float4 qa0 = *reinterpret_cast<const float4*>(gp + 0);
        float4 qa1 = *reinterpret_cast<const float4*>(gp + 4);
        float4 qb0 = *reinterpret_cast<const float4*>(gp + 8);
        float4 qb1 = *reinterpret_cast<const float4*>(gp + 12);
        float4 ra0 = *reinterpret_cast<const float4*>(gp + 16);
        float4 ra1 = *reinterpret_cast<const float4*>(gp + 20);
        float4 rb0 = *reinterpret_cast<const float4*>(gp + 24);
        float4 rb1 = *reinterpret_cast<const float4*>(gp + 28);
        u64 g0A[4] = { pack2(qa0.x,qa0.y), pack2(qa0.z,qa0.w),
                       pack2(qa1.x,qa1.y), pack2(qa1.z,qa1.w) };
        u64 g0B[4] = { pack2(qb0.x,qb0.y), pack2(qb0.z,qb0.w),
                       pack2(qb1.x,qb1.y), pack2(qb1.z,qb1.w) };
        u64 g1A[4] = { pack2(ra0.x,ra0.y), pack2(ra0.z,ra0.w),
                       pack2(ra1.x,ra1.y), pack2(ra1.z,ra1.w) };
        u64 g1B[4] = { pack2(rb0.x,rb0.y), pack2(rb0.z,rb0.w),
                       pack2(rb1.x,rb1.y), pack2(rb1.z,rb1.w) };

        // ================= layer 1: 4 gate chains per seq =================
        u64 dA[4], dB[4];
#pragma unroll
        for (int g = 0; g < 4; g++) {
            fma2(dA[g], g0A[0], wi1[g][0], bias1[g]);
            fma2(dB[g], g0B[0], wi1[g][0], bias1[g]);
        }
#pragma unroll
        for (int j = 1; j < 4; j++) {
#pragma unroll
            for (int g = 0; g < 4; g++) {
                fma2(dA[g], g0A[j], wi1[g][j], dA[g]);
                fma2(dB[g], g0B[j], wi1[g][j], dB[g]);
            }
        }
#pragma unroll
        for (int j = 0; j < 4; j++) {
#pragma unroll
            for (int g = 0; g < 4; g++) {
                fma2(dA[g], g1A[j], wh1[g][j], dA[g]);
                fma2(dB[g], g1B[j], wh1[g][j], dB[g]);
            }
        }
        {
            float2 vi, vf, vg, vo;
            vi = unpack2(dA[0]); vf = unpack2(dA[1]);
            vg = unpack2(dA[2]); vo = unpack2(dA[3]);
            float iA = sig_prescaled(vi.x + vi.y);
            float fA = sig_prescaled(vf.x + vf.y);
            float gA = tanha(vg.x + vg.y);
            float oA = sig_prescaled(vo.x + vo.y);
            c1A = fmaf(fA, c1A, iA * gA);
            h1A = oA * tanha(c1A);

            vi = unpack2(dB[0]); vf = unpack2(dB[1]);
            vg = unpack2(dB[2]); vo = unpack2(dB[3]);
            float iB = sig_prescaled(vi.x + vi.y);
            float fB = sig_prescaled(vf.x + vf.y);
            float gB = tanha(vg.x + vg.y);
            float oB = sig_prescaled(vo.x + vo.y);
            c1B = fmaf(fB, c1B, iB * gB);
            h1B = oB * tanha(c1B);
        }

        __syncwarp();                 // all lanes done reading h1(t-1)
        gp[16 + hid] = h1A;
        gp[24 + hid] = h1B;
        // visibility of h1(t) to next iter's loads is ordered by the
        // __syncwarp after next iter's STS h0 (program order + that barrier)
    }

    // ================= MLP head =================
    float p0A = h1A * w_mlp[hid];
    float p1A = h1A * w_mlp[8 + hid];
    float p0B = h1B * w_mlp[hid];
    float p1B = h1B * w_mlp[8 + hid];
#pragma unroll
    for (int off = 1; off < 8; off <<= 1) {
        p0A += __shfl_xor_sync(0xffffffffu, p0A, off);
        p1A += __shfl_xor_sync(0xffffffffu, p1A, off);
        p0B += __shfl_xor_sync(0xffffffffu, p0B, off);
        p1B += __shfl_xor_sync(0xffffffffu, p1B, off);
    }
    if (hid == 0) {
        float2 oA, oB;
        oA.x = p0A + b_mlp[0];
        oA.y = p1A + b_mlp[1];
        oB.x = p0B + b_mlp[0];
        oB.y = p1B + b_mlp[1];
        reinterpret_cast<float2*>(out)[bA] = oA;
        reinterpret_cast<float2*>(out)[bB] = oB;
    }
}

extern "C" void kernel_launch(void* const* d_in, const int* in_sizes, int n_in,
                              void* d_out, int out_size) {
    const float* input = (const float*)d_in[0];
    const float* w_ih0 = (const float*)d_in[1];
    const float* w_hh0 = (const float*)d_in[2];
    const float* b_ih0 = (const float*)d_in[3];
    const float* b_hh0 = (const float*)d_in[4];
    const float* w_ih1 = (const float*)d_in[5];
    const float* w_hh1 = (const float*)d_in[6];
    const float* b_ih1 = (const float*)d_in[7];
    const float* b_hh1 = (const float*)d_in[8];
    const float* w_mlp = (const float*)d_in[9];
    const float* b_mlp = (const float*)d_in[10];

    const int T = 256, IN = 2;
    int B = in_sizes[0] / (T * IN);

    int threads = (B >> 1) * 8;
    int block = 128;
    int grid = (threads + block - 1) / block;

    lstm_fused4<<<grid, block>>>(input, w_ih0, w_hh0, b_ih0, b_hh0,
                                 w_ih1, w_hh1, b_ih1, b_hh1,
                                 w_mlp, b_mlp, (float*)d_out, B);
}

// round 6
// speedup vs baseline: 2.8309x; 2.8309x over previous
#include <cuda_runtime.h>
#include <cuda_bf16.h>
#include <cstdint>

typedef uint32_t u32;

__device__ __forceinline__ float tanha(float x) {
    float r; asm("tanh.approx.f32 %0, %1;" : "=f"(r) : "f"(x)); return r;
}
// sigmoid(z) = 0.5*tanh(z/2)+0.5; the /2 is pre-folded into weights+biases
__device__ __forceinline__ float sigp(float hz) { return fmaf(tanha(hz), 0.5f, 0.5f); }

// pack (lo,hi) f32 -> bf16x2 (first arg -> low 16 bits)
__device__ __forceinline__ u32 bf2(float lo, float hi) {
    u32 r; asm("cvt.rn.bf16x2.f32 %0, %1, %2;" : "=r"(r) : "f"(hi), "f"(lo)); return r;
}
__device__ __forceinline__ float lo_f32(u32 p) { return __uint_as_float(p << 16); }
__device__ __forceinline__ float hi_f32(u32 p) { return __uint_as_float(p & 0xFFFF0000u); }
__device__ __forceinline__ float rbf(float v) {   // value rounded to bf16, as f32
    return __bfloat162float(__float2bfloat16(v));
}

// D += A * B  (m16n8k16, bf16 in, f32 accum), accumulate in place
__device__ __forceinline__ void mma16816(float* d, u32 a0, u32 a1, u32 a2, u32 a3,
                                         u32 b0, u32 b1) {
    asm("mma.sync.aligned.m16n8k16.row.col.f32.bf16.bf16.f32 "
        "{%0,%1,%2,%3}, {%4,%5,%6,%7}, {%8,%9}, {%0,%1,%2,%3};"
        : "+f"(d[0]), "+f"(d[1]), "+f"(d[2]), "+f"(d[3])
        : "r"(a0), "r"(a1), "r"(a2), "r"(a3), "r"(b0), "r"(b1));
}

// One warp = 16 sequences (MMA M-rows). Per step, per layer, gates are 4
// m16n8k16 MMAs (gate = N-chunk, hidden idx = N). The D fragment's (row,col)
// layout equals the A fragment's (row,k) half layout, so h recirculates in
// registers: no shuffles, no smem, no syncs in the loop. A (h,x) and B (W)
// are split bf16 hi+lo; D = Ahi*Bhi + Alo*Bhi + Ahi*Blo. Bias exact in f32 C.
// Sigmoid rows (i,f,o) pre-scaled by 0.5 => sigmoid = tanh.approx + ffma.
__global__ void __launch_bounds__(128) lstm_mma(
    const float* __restrict__ input,
    const float* __restrict__ w_ih0, const float* __restrict__ w_hh0,
    const float* __restrict__ b_ih0, const float* __restrict__ b_hh0,
    const float* __restrict__ w_ih1, const float* __restrict__ w_hh1,
    const float* __restrict__ b_ih1, const float* __restrict__ b_hh1,
    const float* __restrict__ w_mlp, const float* __restrict__ b_mlp,
    float* __restrict__ out, int B)
{
    const int T = 256;
    int lane = threadIdx.x & 31;
    int gid  = lane >> 2;          // 0..7 : row group / B-fragment n index
    int tg   = lane & 3;           // 0..3 : k/col group
    int warp = (blockIdx.x * (blockDim.x >> 5)) + (threadIdx.x >> 5);
    int wbase = warp * 16;

    int rA = wbase + gid;          // sequence for MMA row gid
    int rB = wbase + gid + 8;      // sequence for MMA row gid+8
    int rAc = (rA < B) ? rA : (B - 1);
    int rBc = (rB < B) ? rB : (B - 1);

    // ---- B fragments (weights), bf16 hi+lo, prescaled ----
    // B[k][n] = s_g * w[g*8+n][k];  n = gid, k = tg*2+{0,1} (b0) / +8 (b1)
    u32 B0h[4][2], B0l[4][2], B1h[4][2], B1l[4][2];
    float be0[4], bo0[4], be1[4], bo1[4];
#pragma unroll
    for (int g = 0; g < 4; g++) {
        int wr = g * 8 + gid;
        float s = (g == 2) ? 1.0f : 0.5f;
        // ---- layer 0: k0-7 = w_hh0, k8,9 = w_ih0, k10-15 = 0 ----
        float w0 = s * w_hh0[wr * 8 + tg * 2];
        float w1 = s * w_hh0[wr * 8 + tg * 2 + 1];
        float w2 = 0.f, w3 = 0.f;
        if (tg == 0) { w2 = s * w_ih0[wr * 2]; w3 = s * w_ih0[wr * 2 + 1]; }
        float h0v = rbf(w0), h1v = rbf(w1), h2v = rbf(w2), h3v = rbf(w3);
        B0h[g][0] = bf2(h0v, h1v);
        B0h[g][1] = bf2(h2v, h3v);
        B0l[g][0] = bf2(w0 - h0v, w1 - h1v);
        B0l[g][1] = bf2(w2 - h2v, w3 - h3v);
        // ---- layer 1: k0-7 = w_ih1 (x h0), k8-15 = w_hh1 (x h1) ----
        float v0 = s * w_ih1[wr * 8 + tg * 2];
        float v1 = s * w_ih1[wr * 8 + tg * 2 + 1];
        float v2 = s * w_hh1[wr * 8 + tg * 2];
        float v3 = s * w_hh1[wr * 8 + tg * 2 + 1];
        float q0 = rbf(v0), q1 = rbf(v1), q2 = rbf(v2), q3 = rbf(v3);
        B1h[g][0] = bf2(q0, q1);
        B1h[g][1] = bf2(q2, q3);
        B1l[g][0] = bf2(v0 - q0, v1 - q1);
        B1l[g][1] = bf2(v2 - q2, v3 - q3);
        // ---- biases (exact, f32, indexed by D col = tg*2+{0,1}) ----
        int hidE = tg * 2;
        be0[g] = s * (b_ih0[g * 8 + hidE]     + b_hh0[g * 8 + hidE]);
        bo0[g] = s * (b_ih0[g * 8 + hidE + 1] + b_hh0[g * 8 + hidE + 1]);
        be1[g] = s * (b_ih1[g * 8 + hidE]     + b_hh1[g * 8 + hidE]);
        bo1[g] = s * (b_ih1[g * 8 + hidE + 1] + b_hh1[g * 8 + hidE + 1]);
    }

    // ---- state ----
    float c0[4] = {0.f, 0.f, 0.f, 0.f};
    float c1[4] = {0.f, 0.f, 0.f, 0.f};
    float h1f[4] = {0.f, 0.f, 0.f, 0.f};
    u32 h0hL = 0, h0hH = 0, h0lL = 0, h0lH = 0;   // h0 A-frag (k0-7), hi/lo
    u32 h1hL = 0, h1hH = 0, h1lL = 0, h1lH = 0;   // h1 A-frag (k8-15 of layer1)

    const float2* xr = reinterpret_cast<const float2*>(input);
    float2 xcA = __ldg(&xr[(size_t)rAc * T]);
    float2 xcB = __ldg(&xr[(size_t)rBc * T]);

    for (int t = 0; t < T; t++) {
        // prefetch next x (t+1)
        int tn = (t < T - 1) ? (t + 1) : t;
        float2 xnA = __ldg(&xr[(size_t)rAc * T + tn]);
        float2 xnB = __ldg(&xr[(size_t)rBc * T + tn]);

        // x packs (k8,9 of layer-0 A): only tg==0 carries data
        u32 xhA = 0, xlA = 0, xhB = 0, xlB = 0;
        if (tg == 0) {
            xhA = bf2(xcA.x, xcA.y);
            xlA = bf2(xcA.x - lo_f32(xhA), xcA.y - hi_f32(xhA));
            xhB = bf2(xcB.x, xcB.y);
            xlB = bf2(xcB.x - lo_f32(xhB), xcB.y - hi_f32(xhB));
        }

        // ================= layer 0 =================
        float d[4][4];
#pragma unroll
        for (int g = 0; g < 4; g++) {
            d[g][0] = be0[g]; d[g][1] = bo0[g];
            d[g][2] = be0[g]; d[g][3] = bo0[g];
            mma16816(d[g], h0hL, h0hH, xhA, xhB, B0l[g][0], B0l[g][1]); // Ahi*Blo
            mma16816(d[g], h0lL, h0lH, xlA, xlB, B0h[g][0], B0h[g][1]); // Alo*Bhi
            mma16816(d[g], h0hL, h0hH, xhA, xhB, B0h[g][0], B0h[g][1]); // Ahi*Bhi
        }
        float h0f[4];
#pragma unroll
        for (int j = 0; j < 4; j++) {
            float iv = sigp(d[0][j]);
            float fv = sigp(d[1][j]);
            float gv = tanha(d[2][j]);
            float ov = sigp(d[3][j]);
            c0[j] = fmaf(fv, c0[j], iv * gv);
            h0f[j] = ov * tanha(c0[j]);
        }
        h0hL = bf2(h0f[0], h0f[1]);
        h0lL = bf2(h0f[0] - lo_f32(h0hL), h0f[1] - hi_f32(h0hL));
        h0hH = bf2(h0f[2], h0f[3]);
        h0lH = bf2(h0f[2] - lo_f32(h0hH), h0f[3] - hi_f32(h0hH));

        // ================= layer 1 =================
#pragma unroll
        for (int g = 0; g < 4; g++) {
            d[g][0] = be1[g]; d[g][1] = bo1[g];
            d[g][2] = be1[g]; d[g][3] = bo1[g];
            mma16816(d[g], h0hL, h0hH, h1hL, h1hH, B1l[g][0], B1l[g][1]);
            mma16816(d[g], h0lL, h0lH, h1lL, h1lH, B1h[g][0], B1h[g][1]);
            mma16816(d[g], h0hL, h0hH, h1hL, h1hH, B1h[g][0], B1h[g][1]);
        }
#pragma unroll
        for (int j = 0; j < 4; j++) {
            float iv = sigp(d[0][j]);
            float fv = sigp(d[1][j]);
            float gv = tanha(d[2][j]);
            float ov = sigp(d[3][j]);
            c1[j] = fmaf(fv, c1[j], iv * gv);
            h1f[j] = ov * tanha(c1[j]);
        }
        h1hL = bf2(h1f[0], h1f[1]);
        h1lL = bf2(h1f[0] - lo_f32(h1hL), h1f[1] - hi_f32(h1hL));
        h1hH = bf2(h1f[2], h1f[3]);
        h1lH = bf2(h1f[2] - lo_f32(h1hH), h1f[3] - hi_f32(h1hH));

        xcA = xnA;
        xcB = xnB;
    }

    // ================= MLP head =================
    // thread holds h1 for (rA, tg*2 / tg*2+1) = h1f[0..1], (rB, ...) = h1f[2..3]
    int hidE = tg * 2;
    float p0A = h1f[0] * w_mlp[hidE]     + h1f[1] * w_mlp[hidE + 1];
    float p1A = h1f[0] * w_mlp[8 + hidE] + h1f[1] * w_mlp[8 + hidE + 1];
    float p0B = h1f[2] * w_mlp[hidE]     + h1f[3] * w_mlp[hidE + 1];
    float p1B = h1f[2] * w_mlp[8 + hidE] + h1f[3] * w_mlp[8 + hidE + 1];
#pragma unroll
    for (int off = 1; off < 4; off <<= 1) {
        p0A += __shfl_xor_sync(0xffffffffu, p0A, off);
        p1A += __shfl_xor_sync(0xffffffffu, p1A, off);
        p0B += __shfl_xor_sync(0xffffffffu, p0B, off);
        p1B += __shfl_xor_sync(0xffffffffu, p1B, off);
    }
    if (tg == 0) {
        if (rA < B) {
            float2 o; o.x = p0A + b_mlp[0]; o.y = p1A + b_mlp[1];
            reinterpret_cast<float2*>(out)[rA] = o;
        }
        if (rB < B) {
            float2 o; o.x = p0B + b_mlp[0]; o.y = p1B + b_mlp[1];
            reinterpret_cast<float2*>(out)[rB] = o;
        }
    }
}

extern "C" void kernel_launch(void* const* d_in, const int* in_sizes, int n_in,
                              void* d_out, int out_size) {
    const float* input = (const float*)d_in[0];
    const float* w_ih0 = (const float*)d_in[1];
    const float* w_hh0 = (const float*)d_in[2];
    const float* b_ih0 = (const float*)d_in[3];
    const float* b_hh0 = (const float*)d_in[4];
    const float* w_ih1 = (const float*)d_in[5];
    const float* w_hh1 = (const float*)d_in[6];
    const float* b_ih1 = (const float*)d_in[7];
    const float* b_hh1 = (const float*)d_in[8];
    const float* w_mlp = (const float*)d_in[9];
    const float* b_mlp = (const float*)d_in[10];

    const int T = 256, IN = 2;
    int B = in_sizes[0] / (T * IN);

    // 16 seqs per warp, 4 warps per block => 64 seqs per block
    int grid = (B + 63) / 64;
    lstm_mma<<<grid, 128>>>(input, w_ih0, w_hh0, b_ih0, b_hh0,
                            w_ih1, w_hh1, b_ih1, b_hh1,
                            w_mlp, b_mlp, (float*)d_out, B);
}

// round 7
// speedup vs baseline: 2.9382x; 1.0379x over previous
#include <cuda_runtime.h>
#include <cuda_bf16.h>
#include <cstdint>

typedef uint32_t u32;

__device__ __forceinline__ float tanha(float x) {
    float r; asm("tanh.approx.f32 %0, %1;" : "=f"(r) : "f"(x)); return r;
}
// sigmoid(z) = 0.5*tanh(z/2)+0.5; /2 pre-folded into weights+biases
__device__ __forceinline__ float sigp(float hz) { return fmaf(tanha(hz), 0.5f, 0.5f); }

// pack (lo,hi) f32 -> bf16x2 (first arg -> low 16 bits)
__device__ __forceinline__ u32 bf2(float lo, float hi) {
    u32 r; asm("cvt.rn.bf16x2.f32 %0, %1, %2;" : "=r"(r) : "f"(hi), "f"(lo)); return r;
}
__device__ __forceinline__ float lo_f32(u32 p) { return __uint_as_float(p << 16); }
__device__ __forceinline__ float hi_f32(u32 p) { return __uint_as_float(p & 0xFFFF0000u); }

// D += A * B  (m16n8k16, bf16 in, f32 accum), accumulate in place
__device__ __forceinline__ void mma16816(float* d, u32 a0, u32 a1, u32 a2, u32 a3,
                                         u32 b0, u32 b1) {
    asm("mma.sync.aligned.m16n8k16.row.col.f32.bf16.bf16.f32 "
        "{%0,%1,%2,%3}, {%4,%5,%6,%7}, {%8,%9}, {%0,%1,%2,%3};"
        : "+f"(d[0]), "+f"(d[1]), "+f"(d[2]), "+f"(d[3])
        : "r"(a0), "r"(a1), "r"(a2), "r"(a3), "r"(b0), "r"(b1));
}

// One warp = 16 sequences. Per step:
//  L0 (1 MMA/gate, depth 1): A = [h0_hi (k0-7) | h0_lo (k8-15)], B = [Whh_bf16
//      | Whh_bf16 replicated] => exact-h x bf16-W. x*W_ih + bias folded into
//      the f32 accumulator init via FFMA (exact).
//  L1 (2 indep MMAs/gate): main A=[h0_hi|h1_hi], corr A=[h0_lo|h1_lo], same
//      bf16 B; merged with FADD.
//  Software pipeline: L0(t+1) MMAs are issued before consuming L1(t) results,
//  overlapping both MMA latencies with activation math.
// D fragment (row,col) layout == A fragment (row,k) layout, so h recirculates
// in registers; no smem/shuffles/syncs in the loop.
__global__ void __launch_bounds__(128, 3) lstm_mma2(
    const float* __restrict__ input,
    const float* __restrict__ w_ih0, const float* __restrict__ w_hh0,
    const float* __restrict__ b_ih0, const float* __restrict__ b_hh0,
    const float* __restrict__ w_ih1, const float* __restrict__ w_hh1,
    const float* __restrict__ b_ih1, const float* __restrict__ b_hh1,
    const float* __restrict__ w_mlp, const float* __restrict__ b_mlp,
    float* __restrict__ out, int B)
{
    const int T = 256;
    int lane = threadIdx.x & 31;
    int gid  = lane >> 2;          // B-fragment n index / D row group
    int tg   = lane & 3;           // k/col group
    int warp = (blockIdx.x * (blockDim.x >> 5)) + (threadIdx.x >> 5);
    int wbase = warp * 16;

    int rA = wbase + gid;
    int rB = wbase + gid + 8;
    int rAc = (rA < B) ? rA : (B - 1);
    int rBc = (rB < B) ? rB : (B - 1);

    // ---- weights (bf16, prescaled): B frags + f32 x-weights + f32 biases ----
    u32 B0[4], B1a[4], B1b[4];
    float wi00[4], wi01[4], wi10[4], wi11[4];
    float be0[4], bo0[4], be1[4], bo1[4];
#pragma unroll
    for (int g = 0; g < 4; g++) {
        int wr = g * 8 + gid;          // B col row (n = gid)
        float s = (g == 2) ? 1.0f : 0.5f;
        B0[g]  = bf2(s * w_hh0[wr * 8 + tg * 2], s * w_hh0[wr * 8 + tg * 2 + 1]);
        B1a[g] = bf2(s * w_ih1[wr * 8 + tg * 2], s * w_ih1[wr * 8 + tg * 2 + 1]);
        B1b[g] = bf2(s * w_hh1[wr * 8 + tg * 2], s * w_hh1[wr * 8 + tg * 2 + 1]);
        int cE = g * 8 + tg * 2;       // D col rows (hid = tg*2, tg*2+1)
        wi00[g] = s * w_ih0[cE * 2];         wi01[g] = s * w_ih0[cE * 2 + 1];
        wi10[g] = s * w_ih0[(cE + 1) * 2];   wi11[g] = s * w_ih0[(cE + 1) * 2 + 1];
        be0[g] = s * (b_ih0[cE] + b_hh0[cE]);
        bo0[g] = s * (b_ih0[cE + 1] + b_hh0[cE + 1]);
        be1[g] = s * (b_ih1[cE] + b_hh1[cE]);
        bo1[g] = s * (b_ih1[cE + 1] + b_hh1[cE + 1]);
    }

    // ---- state ----
    float c0[4] = {0.f, 0.f, 0.f, 0.f};
    float c1[4] = {0.f, 0.f, 0.f, 0.f};
    float h1f[4] = {0.f, 0.f, 0.f, 0.f};
    u32 h0hL = 0, h0hH = 0, h0lL = 0, h0lH = 0;
    u32 h1hL = 0, h1hH = 0, h1lL = 0, h1lH = 0;

    const float2* xr = reinterpret_cast<const float2*>(input);

    // ---- prologue: L0(0) = bias + Wih*x(0)  (h0(-1)=0, so no MMA needed) ----
    float d0[4][4];
    {
        float2 xA = __ldg(&xr[(size_t)rAc * T]);
        float2 xB = __ldg(&xr[(size_t)rBc * T]);
#pragma unroll
        for (int g = 0; g < 4; g++) {
            d0[g][0] = fmaf(wi01[g], xA.y, fmaf(wi00[g], xA.x, be0[g]));
            d0[g][1] = fmaf(wi11[g], xA.y, fmaf(wi10[g], xA.x, bo0[g]));
            d0[g][2] = fmaf(wi01[g], xB.y, fmaf(wi00[g], xB.x, be0[g]));
            d0[g][3] = fmaf(wi11[g], xB.y, fmaf(wi10[g], xB.x, bo0[g]));
        }
    }

    for (int t = 0; t < T; t++) {
        // ---- consume L0(t) -> h0(t) ----
        float h0f[4];
#pragma unroll
        for (int j = 0; j < 4; j++) {
            float iv = sigp(d0[0][j]);
            float fv = sigp(d0[1][j]);
            float gv = tanha(d0[2][j]);
            float ov = sigp(d0[3][j]);
            c0[j] = fmaf(fv, c0[j], iv * gv);
            h0f[j] = ov * tanha(c0[j]);
        }
        h0hL = bf2(h0f[0], h0f[1]);
        h0lL = bf2(h0f[0] - lo_f32(h0hL), h0f[1] - hi_f32(h0hL));
        h0hH = bf2(h0f[2], h0f[3]);
        h0lH = bf2(h0f[2] - lo_f32(h0hH), h0f[3] - hi_f32(h0hH));

        // ---- issue L1(t): main (d1) + correction (e1), independent ----
        float d1[4][4], e1[4][4];
#pragma unroll
        for (int g = 0; g < 4; g++) {
            d1[g][0] = be1[g]; d1[g][1] = bo1[g];
            d1[g][2] = be1[g]; d1[g][3] = bo1[g];
            e1[g][0] = 0.f; e1[g][1] = 0.f; e1[g][2] = 0.f; e1[g][3] = 0.f;
            mma16816(d1[g], h0hL, h0hH, h1hL, h1hH, B1a[g], B1b[g]);
            mma16816(e1[g], h0lL, h0lH, h1lL, h1lH, B1a[g], B1b[g]);
        }

        // ---- issue L0(t+1): init f32 (bias + Wih*x, exact), then 1 MMA/gate ----
        {
            int tn = (t < T - 1) ? (t + 1) : t;
            float2 xA = __ldg(&xr[(size_t)rAc * T + tn]);
            float2 xB = __ldg(&xr[(size_t)rBc * T + tn]);
#pragma unroll
            for (int g = 0; g < 4; g++) {
                d0[g][0] = fmaf(wi01[g], xA.y, fmaf(wi00[g], xA.x, be0[g]));
                d0[g][1] = fmaf(wi11[g], xA.y, fmaf(wi10[g], xA.x, bo0[g]));
                d0[g][2] = fmaf(wi01[g], xB.y, fmaf(wi00[g], xB.x, be0[g]));
                d0[g][3] = fmaf(wi11[g], xB.y, fmaf(wi10[g], xB.x, bo0[g]));
                // A = [h0_hi | h0_lo], B k8-15 replicates B0[g] (exact-h x bf16-W)
                mma16816(d0[g], h0hL, h0hH, h0lL, h0lH, B0[g], B0[g]);
            }
        }

        // ---- consume L1(t) -> h1(t) ----
#pragma unroll
        for (int j = 0; j < 4; j++) {
            float iv = sigp(d1[0][j] + e1[0][j]);
            float fv = sigp(d1[1][j] + e1[1][j]);
            float gv = tanha(d1[2][j] + e1[2][j]);
            float ov = sigp(d1[3][j] + e1[3][j]);
            c1[j] = fmaf(fv, c1[j], iv * gv);
            h1f[j] = ov * tanha(c1[j]);
        }
        h1hL = bf2(h1f[0], h1f[1]);
        h1lL = bf2(h1f[0] - lo_f32(h1hL), h1f[1] - hi_f32(h1hL));
        h1hH = bf2(h1f[2], h1f[3]);
        h1lH = bf2(h1f[2] - lo_f32(h1hH), h1f[3] - hi_f32(h1hH));
    }

    // ================= MLP head =================
    int hidE = tg * 2;
    float p0A = h1f[0] * w_mlp[hidE]     + h1f[1] * w_mlp[hidE + 1];
    float p1A = h1f[0] * w_mlp[8 + hidE] + h1f[1] * w_mlp[8 + hidE + 1];
    float p0B = h1f[2] * w_mlp[hidE]     + h1f[3] * w_mlp[hidE + 1];
    float p1B = h1f[2] * w_mlp[8 + hidE] + h1f[3] * w_mlp[8 + hidE + 1];
#pragma unroll
    for (int off = 1; off < 4; off <<= 1) {
        p0A += __shfl_xor_sync(0xffffffffu, p0A, off);
        p1A += __shfl_xor_sync(0xffffffffu, p1A, off);
        p0B += __shfl_xor_sync(0xffffffffu, p0B, off);
        p1B += __shfl_xor_sync(0xffffffffu, p1B, off);
    }
    if (tg == 0) {
        if (rA < B) {
            float2 o; o.x = p0A + b_mlp[0]; o.y = p1A + b_mlp[1];
            reinterpret_cast<float2*>(out)[rA] = o;
        }
        if (rB < B) {
            float2 o; o.x = p0B + b_mlp[0]; o.y = p1B + b_mlp[1];
            reinterpret_cast<float2*>(out)[rB] = o;
        }
    }
}

extern "C" void kernel_launch(void* const* d_in, const int* in_sizes, int n_in,
                              void* d_out, int out_size) {
    const float* input = (const float*)d_in[0];
    const float* w_ih0 = (const float*)d_in[1];
    const float* w_hh0 = (const float*)d_in[2];
    const float* b_ih0 = (const float*)d_in[3];
    const float* b_hh0 = (const float*)d_in[4];
    const float* w_ih1 = (const float*)d_in[5];
    const float* w_hh1 = (const float*)d_in[6];
    const float* b_ih1 = (const float*)d_in[7];
    const float* b_hh1 = (const float*)d_in[8];
    const float* w_mlp = (const float*)d_in[9];
    const float* b_mlp = (const float*)d_in[10];

    const int T = 256, IN = 2;
    int B = in_sizes[0] / (T * IN);

    // 16 seqs per warp, 4 warps per block => 64 seqs per block
    int grid = (B + 63) / 64;
    lstm_mma2<<<grid, 128>>>(input, w_ih0, w_hh0, b_ih0, b_hh0,
                             w_ih1, w_hh1, b_ih1, b_hh1,
                             w_mlp, b_mlp, (float*)d_out, B);
}